// round 17
// baseline (speedup 1.0000x reference)
#include <cuda_runtime.h>
#include <cuda_bf16.h>

typedef unsigned long long ull;

// Problem constants
#define BB    8
#define NN    4096
#define WROW  128
#define ROWS  (BB*NN)
#define INDIM 16420
#define HID   128
#define NACT  16
#define FCSPLIT 512
#define CK    33           // 512*33 >= 16420
#define NQ    16

#define PREP_PER_B 512     // prep items per batch (8 rows each)
#define SEG       1024     // per-batch queue segment: 512 prep + 256 agg1 + 256 agg2
#define FC1_BASE  (BB*SEG) // 8192
#define TOTAL_BLK (FC1_BASE + FCSPLIT)  // 8704

// Bit layout (permuted): word (rd*4+e), bit l <-> column rd*128 + l*4 + e

// ---------------- scratch ----------------
__device__ unsigned g_bits[(size_t)ROWS * WROW];
__device__ float    g_dinv[ROWS];
__device__ float4   g_v [ROWS];
__device__ float4   g_v2[ROWS];
__device__ float4   g_h2[ROWS];
__device__ float4   g_pa[NQ * ROWS];
__device__ float4   g_pb[NQ * ROWS];
__device__ float    g_zacc[BB * HID];
// pipeline counters (zero-init; every replay restores them to zero)
__device__ unsigned g_prepc[BB];
__device__ unsigned g_ctr0[BB * 16];
__device__ unsigned g_ctr1[BB * 16];
__device__ unsigned g_v2r[BB];
__device__ unsigned g_h2r[BB];
__device__ unsigned g_h2pre;
__device__ unsigned g_h2go;
__device__ unsigned g_fcc;

// ---------------- poll helper ----------------
__device__ __forceinline__ void wait_eq(unsigned* p, unsigned tgt)
{
    unsigned v;
    for (;;) {
        asm volatile("ld.global.cg.u32 %0, [%1];" : "=r"(v) : "l"(p));
        if (v == tgt) break;
        __nanosleep(256);
    }
}

// ---------------- prep item: 8 rows (warp per row) ----------------
__device__ __forceinline__ void prep_item(
    int b, int r, int t, const int* __restrict__ adj,
    const float* __restrict__ x, const float* __restrict__ W1)
{
    int lane = t & 31;
    int row  = b * NN + r * 8 + (t >> 5);
    int i    = row & (NN - 1);

    const int4* arow = (const int4*)(adj + ((size_t)row << 12));
    unsigned*   brow = g_bits + ((size_t)row << 7);
    uint4*      brow4 = (uint4*)brow;

    int tw = (i >> 7) * 4 + (i & 3);
    unsigned tb = 1u << ((i >> 2) & 31);

    int4 buf[8];
#pragma unroll
    for (int p = 0; p < 8; ++p)
        buf[p] = __ldcs(&arow[p * 32 + lane]);

    unsigned cnt = 0;

#pragma unroll 1
    for (int g = 0; g < 4; ++g) {
        int4 cur[8];
#pragma unroll
        for (int p = 0; p < 8; ++p) cur[p] = buf[p];
        if (g < 3) {
#pragma unroll
            for (int p = 0; p < 8; ++p)
                buf[p] = __ldcs(&arow[(g + 1) * 256 + p * 32 + lane]);
        }
#pragma unroll
        for (int p = 0; p < 8; ++p) {
            int rd = g * 8 + p;
            int4 v = cur[p];
            unsigned b0 = __ballot_sync(0xffffffffu, v.x != 0);
            unsigned b1 = __ballot_sync(0xffffffffu, v.y != 0);
            unsigned b2 = __ballot_sync(0xffffffffu, v.z != 0);
            unsigned b3 = __ballot_sync(0xffffffffu, v.w != 0);
            if (lane == 0)
                brow4[rd] = make_uint4(b0, b1, b2, b3);
            cnt += __popc(b0) + __popc(b1) + __popc(b2) + __popc(b3);
        }
    }

    if (lane == 0) {
        unsigned wv = brow[tw];
        cnt += ((wv & tb) == 0u);
        brow[tw] = wv | tb;
        float d = rsqrtf((float)cnt);
        g_dinv[row] = d;
        float x0 = x[row*3], x1 = x[row*3+1], x2 = x[row*3+2];
        float u0 = x0*W1[0] + x1*W1[3] + x2*W1[6];
        float u1 = x0*W1[1] + x1*W1[4] + x2*W1[7];
        float u2 = x0*W1[2] + x1*W1[5] + x2*W1[8];
        g_v[row] = make_float4(d*u0, d*u1, d*u2, 0.f);
    }

    __threadfence();
    __syncthreads();
    if (t == 0) atomicAdd(&g_prepc[b], 1u);
}

// ---------------- quad-LUT aggregation core ----------------
__device__ __forceinline__ void agg_core(
    char* sm, const float4* __restrict__ vin, float4* __restrict__ part,
    int b, int rt, int s, int t)
{
    float2* sxy = (float2*)sm;            // 8 KB
    float*  szl = (float*)(sm + 8192);    // 4 KB

    {
        int quad = t >> 2;
        int j = quad >> 3, k = quad & 7;
        int base = b * NN + s * 256 + (j >> 2) * 128 + k * 16 + (j & 3);
        float4 v0 = vin[base], v1 = vin[base + 4], v2 = vin[base + 8], v3 = vin[base + 12];
        int e0 = (t & 3) * 4;
        float2* exy = &sxy[quad * 16];
        float*  ez  = &szl[quad * 16];
#pragma unroll
        for (int e = 0; e < 4; ++e) {
            int i = e0 + e;
            float sx = 0.f, sy = 0.f, sz = 0.f;
            if (i & 1) { sx += v0.x; sy += v0.y; sz += v0.z; }
            if (i & 2) { sx += v1.x; sy += v1.y; sz += v1.z; }
            if (i & 4) { sx += v2.x; sy += v2.y; sz += v2.z; }
            if (i & 8) { sx += v3.x; sy += v3.y; sz += v3.z; }
            exy[i] = make_float2(sx, sy);
            ez[i]  = sz;
        }
    }
    __syncthreads();

    int row = b * NN + rt * 256 + t;

    const uint4* gw = (const uint4*)(g_bits + (size_t)row * WROW + s * 8);
    uint4 w0 = gw[0], w1 = gw[1];
    unsigned words[8] = { w0.x, w0.y, w0.z, w0.w, w1.x, w1.y, w1.z, w1.w };

    unsigned bxy = (unsigned)__cvta_generic_to_shared(sxy);
    unsigned bz  = (unsigned)__cvta_generic_to_shared(szl);

    ull  accxy0 = 0ull, accxy1 = 0ull;
    float accz0 = 0.f,  accz1 = 0.f;

#pragma unroll
    for (int wl = 0; wl < 8; ++wl) {
        unsigned w = words[wl];
        unsigned rxy = bxy + wl * 1024;
        unsigned rz  = bz  + wl * 512;
#pragma unroll
        for (int k = 0; k < 8; k += 2) {
            unsigned idx0 = (w >> (4 * k)) & 15u;
            unsigned idx1 = (w >> (4 * k + 4)) & 15u;
            unsigned axy0 = rxy + k * 128 + idx0 * 8;
            unsigned axy1 = rxy + k * 128 + 128 + idx1 * 8;
            unsigned az0  = rz  + k * 64 + idx0 * 4;
            unsigned az1  = rz  + k * 64 + 64 + idx1 * 4;
            ull vxy0, vxy1;
            float vz0, vz1;
            asm volatile("ld.shared.b64 %0, [%1];" : "=l"(vxy0) : "r"(axy0));
            asm volatile("ld.shared.b64 %0, [%1];" : "=l"(vxy1) : "r"(axy1));
            asm volatile("ld.shared.f32 %0, [%1];" : "=f"(vz0) : "r"(az0));
            asm volatile("ld.shared.f32 %0, [%1];" : "=f"(vz1) : "r"(az1));
            asm volatile("add.rn.f32x2 %0, %0, %1;" : "+l"(accxy0) : "l"(vxy0));
            asm volatile("add.rn.f32x2 %0, %0, %1;" : "+l"(accxy1) : "l"(vxy1));
            accz0 += vz0;
            accz1 += vz1;
        }
    }

    ull accxy;
    asm volatile("add.rn.f32x2 %0, %1, %2;" : "=l"(accxy) : "l"(accxy0), "l"(accxy1));
    float ax, ay;
    asm volatile("mov.b64 {%0, %1}, %2;" : "=f"(ax), "=f"(ay) : "l"(accxy));
    part[s * ROWS + row] = make_float4(ax, ay, accz0 + accz1, 0.f);
}

// ---------------- mega kernel ----------------
__global__ void __launch_bounds__(256) mega_kernel(
    const int* __restrict__ adj, const float* __restrict__ x,
    const float* __restrict__ y, const float* __restrict__ idxin,
    const float* __restrict__ W1, const float* __restrict__ b1,
    const float* __restrict__ W2, const float* __restrict__ b2,
    const float* __restrict__ fcW1, const float* __restrict__ fcb1,
    const float* __restrict__ fcW2, const float* __restrict__ fcb2,
    float* __restrict__ out)
{
    __shared__ __align__(16) char sm[17472];
    __shared__ unsigned s_r1, s_r2, s_r3;

    int bid = blockIdx.x;
    int t   = threadIdx.x;

    if (bid < FC1_BASE) {
        int b = bid >> 10;
        int r = bid & 1023;

        if (r < PREP_PER_B) {
            // ================= PREP =================
            prep_item(b, r, t, adj, x, W1);
            return;
        }

        if (r < PREP_PER_B + 256) {
            // ================= AGG layer 1 =================
            int q  = r - PREP_PER_B;
            int rt = q >> 4, s = q & 15;
            if (t == 0) wait_eq(&g_prepc[b], PREP_PER_B);
            __syncthreads();

            agg_core(sm, g_v, g_pa, b, rt, s, t);

            __threadfence();
            __syncthreads();
            if (t == 0) s_r1 = atomicAdd(&g_ctr0[b * 16 + rt], 1u);
            __syncthreads();
            if (s_r1 == 15u) {
                if (t == 0) g_ctr0[b * 16 + rt] = 0u;   // self-reset for next replay
                __threadfence();
                int id = b * NN + rt * 256 + t;
                float sx = 0.f, sy = 0.f, sz = 0.f;
#pragma unroll
                for (int qq = 0; qq < NQ; ++qq) {
                    float4 p = __ldcg(&g_pa[qq * ROWS + id]);
                    sx += p.x; sy += p.y; sz += p.z;
                }
                float d = g_dinv[id];
                float h0 = fmaxf(d * sx + b1[0], 0.f);
                float h1 = fmaxf(d * sy + b1[1], 0.f);
                float h2 = fmaxf(d * sz + b1[2], 0.f);
                float u0 = h0*W2[0] + h1*W2[3] + h2*W2[6];
                float u1 = h0*W2[1] + h1*W2[4] + h2*W2[7];
                float u2 = h0*W2[2] + h1*W2[5] + h2*W2[8];
                g_v2[id] = make_float4(d*u0, d*u1, d*u2, 0.f);
                __threadfence();
                __syncthreads();
                if (t == 0) atomicAdd(&g_v2r[b], 1u);
            }
            return;
        }

        // ================= AGG layer 2 =================
        {
            int q  = r - PREP_PER_B - 256;
            int rt = q >> 4, s = q & 15;
            if (t == 0) wait_eq(&g_v2r[b], 16u);
            __syncthreads();

            agg_core(sm, g_v2, g_pb, b, rt, s, t);

            __threadfence();
            __syncthreads();
            if (t == 0) s_r1 = atomicAdd(&g_ctr1[b * 16 + rt], 1u);
            __syncthreads();
            if (s_r1 == 15u) {
                if (t == 0) g_ctr1[b * 16 + rt] = 0u;
                __threadfence();
                int id = b * NN + rt * 256 + t;
                float sx = 0.f, sy = 0.f, sz = 0.f;
#pragma unroll
                for (int qq = 0; qq < NQ; ++qq) {
                    float4 p = __ldcg(&g_pb[qq * ROWS + id]);
                    sx += p.x; sy += p.y; sz += p.z;
                }
                float d = g_dinv[id];
                g_h2[id] = make_float4(d * sx + b2[0], d * sy + b2[1], d * sz + b2[2], 0.f);
                __threadfence();
                __syncthreads();
                if (t == 0) s_r2 = atomicAdd(&g_h2r[b], 1u);
                __syncthreads();
                if (s_r2 == 15u) {
                    // batch b fully done: reset batch counters, count batches
                    if (t == 0) {
                        g_h2r[b] = 0u;
                        g_v2r[b] = 0u;
                        g_prepc[b] = 0u;
                        s_r3 = atomicAdd(&g_h2pre, 1u);
                    }
                    __syncthreads();
                    if (s_r3 == (unsigned)(BB - 1)) {
                        // all 8 batches done: init zacc with bias, open fc1 gate
#pragma unroll
                        for (int rr = 0; rr < 4; ++rr) {
                            int idx = rr * 256 + t;
                            g_zacc[idx] = fcb1[idx & (HID - 1)];
                        }
                        __threadfence();
                        __syncthreads();
                        if (t == 0) atomicExch(&g_h2go, 1u);
                    }
                }
            }
            return;
        }
    }

    // ================= FC1 (+ fused fc2 epilogue) =================
    {
        int s  = bid - FC1_BASE;
        int k0 = s * CK;
        int klen = INDIM - k0;
        if (klen > CK) klen = CK;
        if (klen < 0) klen = 0;
        int warp = t >> 5, lane = t & 31;

        float (*zc)[CK + 1] = (float (*)[CK + 1])sm;                 // 1088 B
        float4* sred = (float4*)(sm + 1088);                          // 16 KB: [4][BB][32]

        if (t == 0) wait_eq(&g_h2go, 1u);
        __syncthreads();

        for (int idx = t; idx < BB * CK; idx += 256) {
            int b  = idx / CK;
            int kk = idx - b * CK;
            float z = 0.f;
            if (kk < klen) {
                int k = k0 + kk;
                if (k < NN) {
                    z = idxin[b * NN + k];
                } else if (k < 4 * NN) {
                    int g = k - NN;
                    int i = g / 3;
                    int f = g - i * 3;
                    z = ((const float*)&g_h2[b * NN + i])[f];
                } else {
                    z = y[b * 36 + (k - 4 * NN)];
                }
            }
            zc[b][kk] = z;
        }
        __syncthreads();

        const float4* W4 = (const float4*)fcW1;
        float4 acc[BB];
#pragma unroll
        for (int b = 0; b < BB; ++b) acc[b] = make_float4(0.f, 0.f, 0.f, 0.f);

        for (int kk = warp; kk < klen; kk += 8) {
            float4 w = W4[(size_t)(k0 + kk) * 32 + lane];
#pragma unroll
            for (int b = 0; b < BB; ++b) {
                float z = zc[b][kk];
                acc[b].x += z * w.x; acc[b].y += z * w.y;
                acc[b].z += z * w.z; acc[b].w += z * w.w;
            }
        }

        // warps 4-7 park partials; warps 0-3 merge, then 128 threads finish
        if (warp >= 4) {
#pragma unroll
            for (int b = 0; b < BB; ++b)
                sred[((warp - 4) * BB + b) * 32 + lane] = acc[b];
        }
        __syncthreads();
        if (warp < 4) {
#pragma unroll
            for (int b = 0; b < BB; ++b) {
                float4 o = sred[(warp * BB + b) * 32 + lane];
                acc[b].x += o.x; acc[b].y += o.y; acc[b].z += o.z; acc[b].w += o.w;
                sred[(warp * BB + b) * 32 + lane] = acc[b];
            }
        }
        __syncthreads();
        if (t < HID) {
#pragma unroll
            for (int b = 0; b < BB; ++b) {
                const float* s0 = (const float*)&sred[(0 * BB + b) * 32];
                const float* s1 = (const float*)&sred[(1 * BB + b) * 32];
                const float* s2 = (const float*)&sred[(2 * BB + b) * 32];
                const float* s3 = (const float*)&sred[(3 * BB + b) * 32];
                atomicAdd(&g_zacc[b * HID + t], (s0[t] + s1[t]) + (s2[t] + s3[t]));
            }
        }

        __threadfence();
        __syncthreads();
        if (t == 0) s_r1 = atomicAdd(&g_fcc, 1u);
        __syncthreads();
        if (s_r1 == (unsigned)(FCSPLIT - 1)) {
            __threadfence();
            if (t < HID) {
                int ob = t >> 4;
                int oa = t & 15;
                float o = fcb2[oa];
#pragma unroll 8
                for (int h = 0; h < HID; ++h)
                    o += fmaxf(__ldcg(&g_zacc[ob * HID + h]), 0.f) * fcW2[h * NACT + oa];
                out[ob * NACT + oa] = o;
            }
            // reset global gate counters for next replay
            if (t == 0) {
                g_fcc = 0u;
                g_h2go = 0u;
                g_h2pre = 0u;
            }
        }
    }
}

// ---------------- launch ----------------
extern "C" void kernel_launch(void* const* d_in, const int* in_sizes, int n_in,
                              void* d_out, int out_size)
{
    const float* idxin = (const float*)d_in[0];   // [8,4096]
    const float* x     = (const float*)d_in[1];   // [8,4096,3]
    const float* y     = (const float*)d_in[2];   // [8,12,3]
    const int*   adj   = (const int*)  d_in[3];   // [8,4096,4096]
    const float* W1    = (const float*)d_in[4];
    const float* b1    = (const float*)d_in[5];
    const float* W2    = (const float*)d_in[6];
    const float* b2    = (const float*)d_in[7];
    const float* fcW1  = (const float*)d_in[8];
    const float* fcb1  = (const float*)d_in[9];
    const float* fcW2  = (const float*)d_in[10];
    const float* fcb2  = (const float*)d_in[11];
    float* out = (float*)d_out;

    mega_kernel<<<TOTAL_BLK, 256>>>(adj, x, y, idxin, W1, b1, W2, b2,
                                    fcW1, fcb1, fcW2, fcb2, out);
}